// round 8
// baseline (speedup 1.0000x reference)
#include <cuda_runtime.h>
#include <cuda_fp16.h>
#include <math.h>

#define NB 16
#define NN 48
#define HID 64
#define MSG 64
#define EDGE 16
#define NL 128
#define TGT 128
#define NE (NB*NN*NN)    // 36864 edges
#define NNODE (NB*NN)    // 768 nodes

// -------- device scratch (static; no allocation) --------
__device__ float2 d_SP[3*129*MSG];   // [sel][c][m], c=128 row = bias prefix (Bp)
__device__ float  d_wiht[HID*3*HID]; // transposed gru_wih: [k][gate*64+c]
__device__ float  d_whht[HID*3*HID]; // transposed gru_whh: [k][gate*64+c]
__device__ unsigned d_w1t[NL*NL];    // msg_w1 transposed [n][k], tf32 bits
__device__ unsigned d_w0t[NL*EDGE];  // msg_w0 transposed [n][k], tf32 bits
__device__ __half d_r2h[NE*NL];      // relu2 fp16, TRANSPOSED: [(b*48+j)*48+i][c]
__device__ float d_gT[NNODE*NN];     // g transposed: [b*48+j][i]
__device__ float d_hf[NNODE*HID];    // h_first
__device__ float d_hA[NNODE*HID];
__device__ float d_hB[NNODE*HID];
__device__ float d_mask[NNODE];
__device__ float d_tmp[NNODE*TGT];

__device__ __forceinline__ unsigned f2tf32(float f) {
    unsigned u;
    asm("cvt.rna.tf32.f32 %0, %1;" : "=r"(u) : "f"(f));
    return u;
}

#define MMA_TF32(c0,c1,c2,c3,a0,a1,a2,a3,b0,b1) \
  asm volatile("mma.sync.aligned.m16n8k8.row.col.f32.tf32.tf32.f32 " \
    "{%0,%1,%2,%3},{%4,%5,%6,%7},{%8,%9},{%0,%1,%2,%3};" \
    : "+f"(c0),"+f"(c1),"+f"(c2),"+f"(c3) \
    : "r"(a0),"r"(a1),"r"(a2),"r"(a3),"r"(b0),"r"(b1))

// -------- mega-prep: all precompute + init in ONE launch --------
// 0..127 SP | 128 Bp | 129..192 w transposes | 193..256 w1t | 257..264 w0t
// 265..520 init | 521..536 gT
__global__ void __launch_bounds__(192) megaprep_kernel(
        const float* __restrict__ w2, const float* __restrict__ b2,
        const float* __restrict__ wih, const float* __restrict__ whh,
        const float* __restrict__ w1, const float* __restrict__ w0,
        const float* __restrict__ h0, const float* __restrict__ g) {
    int blk = blockIdx.x;
    int t = threadIdx.x;
    if (blk < 128) {
        if (t < 64) {
            int c = blk, m = t;
            const float* p = w2 + c*4096 + m*64;
            float acc = 0.f, s16 = 0.f, s32 = 0.f, s48 = 0.f;
            #pragma unroll
            for (int h = 0; h < 64; ++h) {
                acc += p[h];
                if (h == 15) s16 = acc;
                if (h == 31) s32 = acc;
                if (h == 47) s48 = acc;
            }
            d_SP[0*8256 + c*64 + m] = make_float2(s16, acc - s16);
            d_SP[1*8256 + c*64 + m] = make_float2(s32, acc - s32);
            d_SP[2*8256 + c*64 + m] = make_float2(s48, acc - s48);
        }
    } else if (blk == 128) {
        if (t < 64) {
            int m = t;
            const float* q = b2 + m*64;
            float a = 0.f, t16 = 0.f, t32 = 0.f, t48 = 0.f;
            #pragma unroll
            for (int h = 0; h < 64; ++h) {
                a += q[h];
                if (h == 15) t16 = a;
                if (h == 31) t32 = a;
                if (h == 47) t48 = a;
            }
            d_SP[0*8256 + 128*64 + m] = make_float2(t16, a - t16);
            d_SP[1*8256 + 128*64 + m] = make_float2(t32, a - t32);
            d_SP[2*8256 + 128*64 + m] = make_float2(t48, a - t48);
        }
    } else if (blk < 193) {
        int k = blk - 129;
        d_wiht[k*192 + t] = wih[t*64 + k];
        d_whht[k*192 + t] = whh[t*64 + k];
    } else if (blk < 257) {
        int base = (blk - 193)*256;
        for (int idx = t; idx < 256; idx += 192) {
            int i = base + idx;
            int n = i >> 7, k = i & 127;
            d_w1t[i] = f2tf32(w1[k*128 + n]);
        }
    } else if (blk < 265) {
        int base = (blk - 257)*256;
        for (int idx = t; idx < 256; idx += 192) {
            int i = base + idx;
            int n = i >> 4, k = i & 15;
            d_w0t[i] = f2tf32(w0[k*128 + n]);
        }
    } else if (blk < 521) {
        int nb = blk - 265;
        int node = nb*3 + t/64;
        int c = t & 63;
        __shared__ float red[192];
        float v = (c < 32) ? h0[node*32 + c] : 0.f;
        d_hf[node*64 + c] = v;
        red[t] = (c < 32) ? v : 0.f;
        __syncthreads();
        if (c == 0) {
            float s = 0.f;
            int b0 = (t/64)*64;
            #pragma unroll
            for (int i = 0; i < 32; ++i) s += red[b0 + i];
            d_mask[node] = (s > 0.f) ? 1.f : 0.f;
        }
    } else {
        // g transpose: d_gT[(b*48+j)*48 + i] = g[(b*48+i)*48 + j]
        int base = (blk - 521)*2304;
        for (int r = t; r < 2304; r += 192) {
            int gidx = base + r;
            int bj = gidx / 48, i = gidx % 48;
            int b = bj / 48, j = bj % 48;
            d_gT[gidx] = g[(b*48 + i)*48 + j];
        }
    }
}

// -------- edge MLP via tf32 tensor cores; stores fp16 TRANSPOSED to d_r2h --------
#define RELU2_SMEM ((128*132*2 + 128*20*2 + 256)*4)
__global__ void __launch_bounds__(256) relu2_kernel(const float* __restrict__ e,
        const float* __restrict__ b0, const float* __restrict__ b1) {
    extern __shared__ char smem_raw[];
    unsigned* W1U = (unsigned*)smem_raw;
    unsigned* X1U = W1U + 128*132;
    unsigned* ESU = X1U + 128*132;
    unsigned* W0U = ESU + 128*20;
    float* B0S = (float*)(W0U + 128*20);
    float* B1S = B0S + 128;
    int t = threadIdx.x;
    int row0 = blockIdx.x * 128;

    for (int idx = t; idx < 16384; idx += 256) {
        int n = idx >> 7, k = idx & 127;
        W1U[n*132 + k] = d_w1t[idx];
    }
    for (int idx = t; idx < 2048; idx += 256) {
        int r = idx >> 4, k = idx & 15;
        ESU[r*20 + k] = f2tf32(e[row0*16 + idx]);
        W0U[r*20 + k] = d_w0t[idx];
    }
    if (t < 128) { B0S[t] = b0[t]; B1S[t] = b1[t]; }
    __syncthreads();

    int lane = t & 31, warp = t >> 5;
    int rbase = warp * 16;
    int qrow = lane >> 2, qcol = lane & 3;

    float acc[16][4];
    // layer 1: 16 -> 128 (relu)
    #pragma unroll
    for (int nt = 0; nt < 16; ++nt) {
        float bv0 = B0S[nt*8 + 2*qcol], bv1 = B0S[nt*8 + 2*qcol + 1];
        acc[nt][0] = bv0; acc[nt][1] = bv1; acc[nt][2] = bv0; acc[nt][3] = bv1;
    }
    #pragma unroll
    for (int kt = 0; kt < 2; ++kt) {
        unsigned a0 = ESU[(rbase+qrow  )*20 + kt*8 + qcol];
        unsigned a1 = ESU[(rbase+qrow+8)*20 + kt*8 + qcol];
        unsigned a2 = ESU[(rbase+qrow  )*20 + kt*8 + 4 + qcol];
        unsigned a3 = ESU[(rbase+qrow+8)*20 + kt*8 + 4 + qcol];
        #pragma unroll
        for (int nt = 0; nt < 16; ++nt) {
            unsigned bb0 = W0U[(nt*8+qrow)*20 + kt*8 + qcol];
            unsigned bb1 = W0U[(nt*8+qrow)*20 + kt*8 + 4 + qcol];
            MMA_TF32(acc[nt][0],acc[nt][1],acc[nt][2],acc[nt][3],a0,a1,a2,a3,bb0,bb1);
        }
    }
    #pragma unroll
    for (int nt = 0; nt < 16; ++nt) {
        X1U[(rbase+qrow  )*132 + nt*8 + 2*qcol    ] = f2tf32(fmaxf(acc[nt][0], 0.f));
        X1U[(rbase+qrow  )*132 + nt*8 + 2*qcol + 1] = f2tf32(fmaxf(acc[nt][1], 0.f));
        X1U[(rbase+qrow+8)*132 + nt*8 + 2*qcol    ] = f2tf32(fmaxf(acc[nt][2], 0.f));
        X1U[(rbase+qrow+8)*132 + nt*8 + 2*qcol + 1] = f2tf32(fmaxf(acc[nt][3], 0.f));
    }
    __syncthreads();

    // layer 2: 128 -> 128 (relu)
    #pragma unroll
    for (int nt = 0; nt < 16; ++nt) {
        float bv0 = B1S[nt*8 + 2*qcol], bv1 = B1S[nt*8 + 2*qcol + 1];
        acc[nt][0] = bv0; acc[nt][1] = bv1; acc[nt][2] = bv0; acc[nt][3] = bv1;
    }
    #pragma unroll
    for (int kt = 0; kt < 16; ++kt) {
        unsigned a0 = X1U[(rbase+qrow  )*132 + kt*8 + qcol];
        unsigned a1 = X1U[(rbase+qrow+8)*132 + kt*8 + qcol];
        unsigned a2 = X1U[(rbase+qrow  )*132 + kt*8 + 4 + qcol];
        unsigned a3 = X1U[(rbase+qrow+8)*132 + kt*8 + 4 + qcol];
        #pragma unroll
        for (int nt = 0; nt < 16; ++nt) {
            unsigned bb0 = W1U[(nt*8+qrow)*132 + kt*8 + qcol];
            unsigned bb1 = W1U[(nt*8+qrow)*132 + kt*8 + 4 + qcol];
            MMA_TF32(acc[nt][0],acc[nt][1],acc[nt][2],acc[nt][3],a0,a1,a2,a3,bb0,bb1);
        }
    }
    __syncthreads();  // all warps done reading X1U

    // pack relu outputs as half2 into smem (row stride 68 half2 = 272B, 16B-aligned)
    __half2* H = (__half2*)X1U;
    #pragma unroll
    for (int nt = 0; nt < 16; ++nt) {
        H[(rbase+qrow  )*68 + nt*4 + qcol] =
            __floats2half2_rn(fmaxf(acc[nt][0],0.f), fmaxf(acc[nt][1],0.f));
        H[(rbase+qrow+8)*68 + nt*4 + qcol] =
            __floats2half2_rn(fmaxf(acc[nt][2],0.f), fmaxf(acc[nt][3],0.f));
    }
    __syncthreads();
    // transposed store: logical row (b,i,j) -> slot (b,j,i); 16B chunks
    for (int idx = t; idx < 2048; idx += 256) {
        int r = idx >> 4, chunk = idx & 15;
        int row = row0 + r;
        int b = row / 2304; int rem = row - b*2304;
        int i = rem / 48;   int j = rem - i*48;
        uint4 v = *(const uint4*)((const char*)(H + r*68) + chunk*16);
        *(uint4*)(d_r2h + (size_t)((b*48 + j)*48 + i)*128 + chunk*8) = v;
    }
}

// -------- fused layer: 4 nodes (same j, 4 b's) per CTA, 256 threads --------
__global__ void __launch_bounds__(256) layer_kernel(int inbuf, int outbuf,
        const float* __restrict__ bih, const float* __restrict__ bhh) {
    const float* h_in  = (inbuf  == 0) ? d_hf : ((inbuf  == 1) ? d_hA : d_hB);
    float*       h_out = (outbuf == 1) ? d_hA : d_hB;
    int j = blockIdx.x; int b0 = blockIdx.y * 4;
    int t = threadIdx.x;
    int k0 = (4*j)/3;
    int a64 = (16*j) % 48;            // = (64j mod 48), in {0,16,32}
    int sel = (48 - a64)/16 - 1;      // 0->2, 16->1, 32->0

    __shared__ float a_s[4][48][2];
    __shared__ float hold[4][64];
    __shared__ float4 Ppart[2][4][64];
    __shared__ float2 Pst[4][129];    // c=128 holds (Q0,Q1)
    __shared__ float part[2][4][64];
    __shared__ float aggs[4][64];
    __shared__ float gis[4][192];
    __shared__ float ghs[4][192];

    // ---- Phase A: gather g*h (coalesced via d_gT) + own-node hidden ----
    if (t < 192) {
        int bb = t / 48, i = t % 48;
        int bj = (b0+bb)*48 + j;
        int bi = (b0+bb)*48 + i;
        float gv = __ldg(&d_gT[bj*48 + i]);
        a_s[bb][i][0] = gv * h_in[bi*64 + k0];
        a_s[bb][i][1] = gv * h_in[bi*64 + k0 + 1];
    } else {
        int c = t - 192;
        #pragma unroll
        for (int bb = 0; bb < 4; ++bb)
            hold[bb][c] = h_in[((b0+bb)*48 + j)*64 + c];
    }
    __syncthreads();

    // ---- Phase B: P (t<128, 4 nodes, 2-way i split) | gh GEMV (128..191) | Q (192..199) ----
    if (t < 128) {
        int cp = t & 63, ih = t >> 6;
        const __half2* r2p[4];
        #pragma unroll
        for (int bb = 0; bb < 4; ++bb)
            r2p[bb] = (const __half2*)(d_r2h + (size_t)((b0+bb)*48 + j)*6144) + cp;
        float p00[4] = {0,0,0,0}, p01[4] = {0,0,0,0};
        float p10[4] = {0,0,0,0}, p11[4] = {0,0,0,0};
        int ibeg = ih*24;
        #pragma unroll 4
        for (int i = ibeg; i < ibeg + 24; ++i) {
            #pragma unroll
            for (int bb = 0; bb < 4; ++bb) {
                float2 r2v = __half22float2(__ldg(&r2p[bb][i*64]));
                float a0 = a_s[bb][i][0], a1 = a_s[bb][i][1];
                p00[bb] += a0*r2v.x; p01[bb] += a0*r2v.y;
                p10[bb] += a1*r2v.x; p11[bb] += a1*r2v.y;
            }
        }
        #pragma unroll
        for (int bb = 0; bb < 4; ++bb)
            Ppart[ih][bb][cp] = make_float4(p00[bb], p01[bb], p10[bb], p11[bb]);
    } else if (t < 192) {
        int u = t - 128;
        float acc[3][4];
        #pragma unroll
        for (int q = 0; q < 3; ++q)
            #pragma unroll
            for (int bb = 0; bb < 4; ++bb) acc[q][bb] = 0.f;
        #pragma unroll 4
        for (int k = 0; k < 64; ++k) {
            float w0 = __ldg(&d_whht[k*192 + u]);
            float w1 = __ldg(&d_whht[k*192 + 64 + u]);
            float w2 = __ldg(&d_whht[k*192 + 128 + u]);
            #pragma unroll
            for (int bb = 0; bb < 4; ++bb) {
                float hv = hold[bb][k];
                acc[0][bb] += w0*hv; acc[1][bb] += w1*hv; acc[2][bb] += w2*hv;
            }
        }
        float bh0 = bhh[u], bh1 = bhh[64+u], bh2 = bhh[128+u];
        #pragma unroll
        for (int bb = 0; bb < 4; ++bb) {
            ghs[bb][u]       = acc[0][bb] + bh0;
            ghs[bb][64+u]    = acc[1][bb] + bh1;
            ghs[bb][128+u]   = acc[2][bb] + bh2;
        }
    } else if (t < 200) {
        int u = t - 192, bb = u >> 1, s = u & 1;
        float q = 0.f;
        #pragma unroll
        for (int i = 0; i < 48; ++i) q += a_s[bb][i][s];
        if (s == 0) Pst[bb][128].x = q; else Pst[bb][128].y = q;
    }
    __syncthreads();

    // combine Ppart -> Pst (c-major)
    {
        int bb = t >> 6, c0 = t & 63;
        #pragma unroll
        for (int q = 0; q < 2; ++q) {
            int c = c0 + q*64;
            int cp = c >> 1, lo = c & 1;
            float4 A = Ppart[0][bb][cp], B = Ppart[1][bb][cp];
            Pst[bb][c] = lo ? make_float2(A.y + B.y, A.w + B.w)
                            : make_float2(A.x + B.x, A.z + B.z);
        }
    }
    __syncthreads();

    // ---- Phase C: agg[bb][m] = sum_c SP[c][m].P[bb][c]  (c=128 row = bias*Q) ----
    if (t < 128) {
        int m = t & 63, half = t >> 6;
        const float2* SP = d_SP + sel*8256 + m;
        float acc[4] = {0,0,0,0};
        int cbeg = half*64;
        int cend = half ? 129 : 64;
        #pragma unroll 4
        for (int c = cbeg; c < cend; ++c) {
            float2 sp = __ldg(&SP[c*64]);
            #pragma unroll
            for (int bb = 0; bb < 4; ++bb) {
                float2 p = Pst[bb][c];
                acc[bb] += sp.x*p.x + sp.y*p.y;
            }
        }
        #pragma unroll
        for (int bb = 0; bb < 4; ++bb) part[half][bb][m] = acc[bb];
    }
    __syncthreads();
    {
        int bb = t >> 6, m = t & 63;
        aggs[bb][m] = part[0][bb][m] + part[1][bb][m];
    }
    __syncthreads();

    // ---- Phase D: gi[bb][gc] = Wih.agg ----
    if (t < 192) {
        int gc = t;
        float acc[4] = {0,0,0,0};
        #pragma unroll 4
        for (int k = 0; k < 64; ++k) {
            float w = __ldg(&d_wiht[k*192 + gc]);
            #pragma unroll
            for (int bb = 0; bb < 4; ++bb)
                acc[bb] += w * aggs[bb][k];
        }
        #pragma unroll
        for (int bb = 0; bb < 4; ++bb) gis[bb][gc] = acc[bb];
    }
    __syncthreads();

    // ---- Phase E: GRU combine ----
    {
        int bb = t >> 6, c = t & 63;
        int node = (b0+bb)*48 + j;
        float r = 1.f/(1.f+expf(-(gis[bb][c]      + bih[c]      + ghs[bb][c])));
        float z = 1.f/(1.f+expf(-(gis[bb][64+c]   + bih[64+c]   + ghs[bb][64+c])));
        float n = tanhf(gis[bb][128+c] + bih[128+c] + r*ghs[bb][128+c]);
        float hn = (1.f-z)*n + z*hold[bb][c];
        h_out[node*64 + c] = d_mask[node]*hn;
    }
}

// -------- readout: 4 nodes per CTA, float4 over rows --------
__global__ void __launch_bounds__(128) readout_kernel(
   const float* __restrict__ r0w0, const float* __restrict__ r0b0,
   const float* __restrict__ r0w1, const float* __restrict__ r0b1,
   const float* __restrict__ r0w2, const float* __restrict__ r0b2,
   const float* __restrict__ r1w0, const float* __restrict__ r1b0,
   const float* __restrict__ r1w1, const float* __restrict__ r1b1,
   const float* __restrict__ r1w2, const float* __restrict__ r1b2) {
    __shared__ float4 xinv[128];
    __shared__ float4 bufA[128];
    __shared__ float4 bufB[128];
    int c = threadIdx.x;
    int n0 = blockIdx.x * 4;
    {
        float v[4];
        #pragma unroll
        for (int r = 0; r < 4; ++r)
            v[r] = (c < 64) ? d_hf[(n0+r)*64 + c] : d_hA[(n0+r)*64 + (c-64)];
        xinv[c] = make_float4(v[0], v[1], v[2], v[3]);
    }
    __syncthreads();

    float4 acc;
    { float b = r0b0[c]; acc = make_float4(b,b,b,b); }
    #pragma unroll 4
    for (int k = 0; k < 128; ++k) {
        float w = __ldg(&r0w0[k*128+c]); float4 x = xinv[k];
        acc.x += x.x*w; acc.y += x.y*w; acc.z += x.z*w; acc.w += x.w*w;
    }
    bufA[c] = make_float4(fmaxf(acc.x,0.f), fmaxf(acc.y,0.f), fmaxf(acc.z,0.f), fmaxf(acc.w,0.f));
    __syncthreads();
    { float b = r0b1[c]; acc = make_float4(b,b,b,b); }
    #pragma unroll 4
    for (int k = 0; k < 128; ++k) {
        float w = __ldg(&r0w1[k*128+c]); float4 x = bufA[k];
        acc.x += x.x*w; acc.y += x.y*w; acc.z += x.z*w; acc.w += x.w*w;
    }
    bufB[c] = make_float4(fmaxf(acc.x,0.f), fmaxf(acc.y,0.f), fmaxf(acc.z,0.f), fmaxf(acc.w,0.f));
    __syncthreads();
    float4 out0;
    { float b = r0b2[c]; out0 = make_float4(b,b,b,b); }
    #pragma unroll 4
    for (int k = 0; k < 128; ++k) {
        float w = __ldg(&r0w2[k*128+c]); float4 x = bufB[k];
        out0.x += x.x*w; out0.y += x.y*w; out0.z += x.z*w; out0.w += x.w*w;
    }
    { float b = r1b0[c]; acc = make_float4(b,b,b,b); }
    #pragma unroll 4
    for (int k = 0; k < 64; ++k) {
        float w = __ldg(&r1w0[k*128+c]); float4 x = xinv[64+k];
        acc.x += x.x*w; acc.y += x.y*w; acc.z += x.z*w; acc.w += x.w*w;
    }
    bufA[c] = make_float4(fmaxf(acc.x,0.f), fmaxf(acc.y,0.f), fmaxf(acc.z,0.f), fmaxf(acc.w,0.f));
    __syncthreads();
    { float b = r1b1[c]; acc = make_float4(b,b,b,b); }
    #pragma unroll 4
    for (int k = 0; k < 128; ++k) {
        float w = __ldg(&r1w1[k*128+c]); float4 x = bufA[k];
        acc.x += x.x*w; acc.y += x.y*w; acc.z += x.z*w; acc.w += x.w*w;
    }
    bufB[c] = make_float4(fmaxf(acc.x,0.f), fmaxf(acc.y,0.f), fmaxf(acc.z,0.f), fmaxf(acc.w,0.f));
    __syncthreads();
    float4 out1;
    { float b = r1b2[c]; out1 = make_float4(b,b,b,b); }
    #pragma unroll 4
    for (int k = 0; k < 128; ++k) {
        float w = __ldg(&r1w2[k*128+c]); float4 x = bufB[k];
        out1.x += x.x*w; out1.y += x.y*w; out1.z += x.z*w; out1.w += x.w*w;
    }
    d_tmp[(n0+0)*128 + c] = d_mask[n0+0]*out0.x*out1.x;
    d_tmp[(n0+1)*128 + c] = d_mask[n0+1]*out0.y*out1.y;
    d_tmp[(n0+2)*128 + c] = d_mask[n0+2]*out0.z*out1.z;
    d_tmp[(n0+3)*128 + c] = d_mask[n0+3]*out0.w*out1.w;
}

// -------- final node-sum + sigmoid --------
__global__ void reduce_kernel(float* __restrict__ out) {
    int b = blockIdx.x; int t = threadIdx.x;  // 128 threads
    float s = 0.f;
    #pragma unroll 4
    for (int j = 0; j < 48; ++j) s += d_tmp[(b*48+j)*128 + t];
    out[b*128+t] = 1.f/(1.f+expf(-s));
}

extern "C" void kernel_launch(void* const* d_in, const int* in_sizes, int n_in,
                              void* d_out, int out_size) {
    const float* g       = (const float*)d_in[0];
    const float* h0      = (const float*)d_in[1];
    const float* e       = (const float*)d_in[2];
    const float* msg_w0  = (const float*)d_in[3];
    const float* msg_b0  = (const float*)d_in[4];
    const float* msg_w1  = (const float*)d_in[5];
    const float* msg_b1  = (const float*)d_in[6];
    const float* msg_w2  = (const float*)d_in[7];
    const float* msg_b2  = (const float*)d_in[8];
    const float* gru_wih = (const float*)d_in[9];
    const float* gru_whh = (const float*)d_in[10];
    const float* gru_bih = (const float*)d_in[11];
    const float* gru_bhh = (const float*)d_in[12];
    const float* r0_w0   = (const float*)d_in[13];
    const float* r0_b0   = (const float*)d_in[14];
    const float* r0_w1   = (const float*)d_in[15];
    const float* r0_b1   = (const float*)d_in[16];
    const float* r0_w2   = (const float*)d_in[17];
    const float* r0_b2   = (const float*)d_in[18];
    const float* r1_w0   = (const float*)d_in[19];
    const float* r1_b0   = (const float*)d_in[20];
    const float* r1_w1   = (const float*)d_in[21];
    const float* r1_b1   = (const float*)d_in[22];
    const float* r1_w2   = (const float*)d_in[23];
    const float* r1_b2   = (const float*)d_in[24];
    float* out = (float*)d_out;

    cudaFuncSetAttribute(relu2_kernel, cudaFuncAttributeMaxDynamicSharedMemorySize, RELU2_SMEM);

    megaprep_kernel<<<537, 192>>>(msg_w2, msg_b2, gru_wih, gru_whh, msg_w1, msg_w0, h0, g);
    relu2_kernel<<<NE/128, 256, RELU2_SMEM>>>(e, msg_b0, msg_b1);
    // L1: hf -> hA ; L2: hA -> hB ; L3: hB -> hA
    layer_kernel<<<dim3(48, 4), 256>>>(0, 1, gru_bih, gru_bhh);
    layer_kernel<<<dim3(48, 4), 256>>>(1, 2, gru_bih, gru_bhh);
    layer_kernel<<<dim3(48, 4), 256>>>(2, 1, gru_bih, gru_bhh);
    readout_kernel<<<NNODE/4, 128>>>(r0_w0, r0_b0, r0_w1, r0_b1, r0_w2, r0_b2,
                                     r1_w0, r1_b0, r1_w1, r1_b1, r1_w2, r1_b2);
    reduce_kernel<<<NB, 128>>>(out);
}

// round 9
// speedup vs baseline: 1.0589x; 1.0589x over previous
#include <cuda_runtime.h>
#include <cuda_fp16.h>
#include <math.h>

#define NB 16
#define NN 48
#define HID 64
#define MSG 64
#define EDGE 16
#define NL 128
#define TGT 128
#define NE (NB*NN*NN)    // 36864 edges
#define NNODE (NB*NN)    // 768 nodes

// -------- device scratch (static; no allocation) --------
__device__ float4 d_SPq[3*64*64];    // [sel][cq][m] = (SP[2cq][m].xy, SP[2cq+1][m].xy)
__device__ float2 d_SPb[3*64];       // bias prefix row [sel][m]
__device__ float4 d_wihq[16*192];    // [kq][gc] = wih[gc][4kq..4kq+3]
__device__ float4 d_whhq[16*192];    // [kq][gc] = whh[gc][4kq..4kq+3]
__device__ unsigned d_w1t[NL*NL];    // msg_w1 transposed [n][k], tf32 bits
__device__ unsigned d_w0t[NL*EDGE];  // msg_w0 transposed [n][k], tf32 bits
__device__ __half d_r2h[NE*NL];      // relu2 fp16, TRANSPOSED: [(b*48+j)*48+i][c]
__device__ float d_gT[NNODE*NN];     // g transposed: [b*48+j][i]
__device__ float d_hf[NNODE*HID];    // h_first (normal layout)
__device__ float d_hA[NNODE*HID];
__device__ float d_hB[NNODE*HID];
__device__ float d_hfT[HID*NNODE];   // transposed: [c][node]
__device__ float d_hAT[HID*NNODE];
__device__ float d_hBT[HID*NNODE];
__device__ float d_gh[NNODE*192];    // pipelined hidden gates (incl. bhh)
__device__ float d_mask[NNODE];
__device__ float d_tmp[NNODE*TGT];
// readout weights, float4-packed over k-quads: [kq][c]
__device__ float4 d_q0w0[32*128];
__device__ float4 d_q0w1[32*128];
__device__ float4 d_q0w2[32*128];
__device__ float4 d_q1w0[16*128];
__device__ float4 d_q1w1[32*128];
__device__ float4 d_q1w2[32*128];

__device__ __forceinline__ unsigned f2tf32(float f) {
    unsigned u;
    asm("cvt.rna.tf32.f32 %0, %1;" : "=r"(u) : "f"(f));
    return u;
}

#define MMA_TF32(c0,c1,c2,c3,a0,a1,a2,a3,b0,b1) \
  asm volatile("mma.sync.aligned.m16n8k8.row.col.f32.tf32.tf32.f32 " \
    "{%0,%1,%2,%3},{%4,%5,%6,%7},{%8,%9},{%0,%1,%2,%3};" \
    : "+f"(c0),"+f"(c1),"+f"(c2),"+f"(c3) \
    : "r"(a0),"r"(a1),"r"(a2),"r"(a3),"r"(b0),"r"(b1))

// -------- mega-prep --------
// 0..127 SPq | 128 SPb | 129..144 wihq | 145..160 whhq | 161..166 readout repack
// 167..422 init+hfT+mask+gh0 (3 nodes) | 423..438 gT | 439..502 w1t | 503..510 w0t
__global__ void __launch_bounds__(192) megaprep_kernel(
        const float* __restrict__ w2, const float* __restrict__ b2,
        const float* __restrict__ wih, const float* __restrict__ whh,
        const float* __restrict__ bhh,
        const float* __restrict__ w1, const float* __restrict__ w0,
        const float* __restrict__ h0, const float* __restrict__ g,
        const float* __restrict__ r0w0, const float* __restrict__ r0w1,
        const float* __restrict__ r0w2, const float* __restrict__ r1w0,
        const float* __restrict__ r1w1, const float* __restrict__ r1w2) {
    int blk = blockIdx.x;
    int t = threadIdx.x;
    if (blk < 128) {
        if (t < 64) {
            int c = blk, m = t;
            const float* p = w2 + c*4096 + m*64;
            float acc = 0.f, s16 = 0.f, s32 = 0.f, s48 = 0.f;
            #pragma unroll
            for (int h = 0; h < 64; ++h) {
                acc += p[h];
                if (h == 15) s16 = acc;
                if (h == 31) s32 = acc;
                if (h == 47) s48 = acc;
            }
            int cq = c >> 1, par = c & 1;
            float2* spq2 = (float2*)d_SPq;
            spq2[((0*64 + cq)*64 + m)*2 + par] = make_float2(s16, acc - s16);
            spq2[((1*64 + cq)*64 + m)*2 + par] = make_float2(s32, acc - s32);
            spq2[((2*64 + cq)*64 + m)*2 + par] = make_float2(s48, acc - s48);
        }
    } else if (blk == 128) {
        if (t < 64) {
            int m = t;
            const float* q = b2 + m*64;
            float a = 0.f, t16 = 0.f, t32 = 0.f, t48 = 0.f;
            #pragma unroll
            for (int h = 0; h < 64; ++h) {
                a += q[h];
                if (h == 15) t16 = a;
                if (h == 31) t32 = a;
                if (h == 47) t48 = a;
            }
            d_SPb[0*64+m] = make_float2(t16, a - t16);
            d_SPb[1*64+m] = make_float2(t32, a - t32);
            d_SPb[2*64+m] = make_float2(t48, a - t48);
        }
    } else if (blk < 145) {
        int kq = blk - 129;
        d_wihq[kq*192 + t] = *(const float4*)&wih[t*64 + 4*kq];
    } else if (blk < 161) {
        int kq = blk - 145;
        d_whhq[kq*192 + t] = *(const float4*)&whh[t*64 + 4*kq];
    } else if (blk < 167) {
        int mat = blk - 161;
        const float* src; float4* dst; int nkq;
        if (mat == 0)      { src = r0w0; dst = d_q0w0; nkq = 32; }
        else if (mat == 1) { src = r0w1; dst = d_q0w1; nkq = 32; }
        else if (mat == 2) { src = r0w2; dst = d_q0w2; nkq = 32; }
        else if (mat == 3) { src = r1w0; dst = d_q1w0; nkq = 16; }
        else if (mat == 4) { src = r1w1; dst = d_q1w1; nkq = 32; }
        else               { src = r1w2; dst = d_q1w2; nkq = 32; }
        int total = nkq * 128;
        for (int idx = t; idx < total; idx += 192) {
            int kq = idx >> 7, c = idx & 127;
            float4 v;
            v.x = src[(4*kq+0)*128 + c];
            v.y = src[(4*kq+1)*128 + c];
            v.z = src[(4*kq+2)*128 + c];
            v.w = src[(4*kq+3)*128 + c];
            dst[idx] = v;
        }
    } else if (blk < 423) {
        int nb = blk - 167;
        int node = nb*3 + t/64;
        int c = t & 63;
        __shared__ float red[192];
        float v = (c < 32) ? h0[node*32 + c] : 0.f;
        d_hf[node*64 + c] = v;
        d_hfT[c*768 + node] = v;
        red[t] = v;
        __syncthreads();
        if (c == 0) {
            float s = 0.f;
            int b0 = (t/64)*64;
            #pragma unroll
            for (int i = 0; i < 32; ++i) s += red[b0 + i];
            d_mask[node] = (s > 0.f) ? 1.f : 0.f;
        }
        // gh0 = Whh . h_first + bhh for each of the 3 nodes
        int gc = t;
        float bh = bhh[gc];
        #pragma unroll
        for (int nn = 0; nn < 3; ++nn) {
            float acc = 0.f;
            #pragma unroll 4
            for (int kq = 0; kq < 16; ++kq) {
                float4 w = *(const float4*)&whh[gc*64 + 4*kq];
                acc += w.x*red[nn*64 + 4*kq]   + w.y*red[nn*64 + 4*kq+1]
                     + w.z*red[nn*64 + 4*kq+2] + w.w*red[nn*64 + 4*kq+3];
            }
            d_gh[(nb*3 + nn)*192 + gc] = acc + bh;
        }
    } else if (blk < 439) {
        // g transpose: d_gT[(b*48+j)*48 + i] = g[(b*48+i)*48 + j]
        int base = (blk - 423)*2304;
        for (int r = t; r < 2304; r += 192) {
            int gidx = base + r;
            int bj = gidx / 48, i = gidx % 48;
            int b = bj / 48, j = bj % 48;
            d_gT[gidx] = g[(b*48 + i)*48 + j];
        }
    } else if (blk < 503) {
        int base = (blk - 439)*256;
        for (int idx = t; idx < 256; idx += 192) {
            int i = base + idx;
            int n = i >> 7, k = i & 127;
            d_w1t[i] = f2tf32(w1[k*128 + n]);
        }
    } else {
        int base = (blk - 503)*256;
        for (int idx = t; idx < 256; idx += 192) {
            int i = base + idx;
            int n = i >> 4, k = i & 15;
            d_w0t[i] = f2tf32(w0[k*128 + n]);
        }
    }
}

// -------- edge MLP via tf32 tensor cores; stores fp16 TRANSPOSED to d_r2h --------
#define RELU2_SMEM ((128*132*2 + 128*20*2 + 256)*4)
__global__ void __launch_bounds__(256) relu2_kernel(const float* __restrict__ e,
        const float* __restrict__ b0, const float* __restrict__ b1) {
    extern __shared__ char smem_raw[];
    unsigned* W1U = (unsigned*)smem_raw;
    unsigned* X1U = W1U + 128*132;
    unsigned* ESU = X1U + 128*132;
    unsigned* W0U = ESU + 128*20;
    float* B0S = (float*)(W0U + 128*20);
    float* B1S = B0S + 128;
    int t = threadIdx.x;
    int row0 = blockIdx.x * 128;

    for (int idx = t; idx < 16384; idx += 256) {
        int n = idx >> 7, k = idx & 127;
        W1U[n*132 + k] = d_w1t[idx];
    }
    for (int idx = t; idx < 2048; idx += 256) {
        int r = idx >> 4, k = idx & 15;
        ESU[r*20 + k] = f2tf32(e[row0*16 + idx]);
        W0U[r*20 + k] = d_w0t[idx];
    }
    if (t < 128) { B0S[t] = b0[t]; B1S[t] = b1[t]; }
    __syncthreads();

    int lane = t & 31, warp = t >> 5;
    int rbase = warp * 16;
    int qrow = lane >> 2, qcol = lane & 3;

    float acc[16][4];
    // layer 1: 16 -> 128 (relu)
    #pragma unroll
    for (int nt = 0; nt < 16; ++nt) {
        float bv0 = B0S[nt*8 + 2*qcol], bv1 = B0S[nt*8 + 2*qcol + 1];
        acc[nt][0] = bv0; acc[nt][1] = bv1; acc[nt][2] = bv0; acc[nt][3] = bv1;
    }
    #pragma unroll
    for (int kt = 0; kt < 2; ++kt) {
        unsigned a0 = ESU[(rbase+qrow  )*20 + kt*8 + qcol];
        unsigned a1 = ESU[(rbase+qrow+8)*20 + kt*8 + qcol];
        unsigned a2 = ESU[(rbase+qrow  )*20 + kt*8 + 4 + qcol];
        unsigned a3 = ESU[(rbase+qrow+8)*20 + kt*8 + 4 + qcol];
        #pragma unroll
        for (int nt = 0; nt < 16; ++nt) {
            unsigned bb0 = W0U[(nt*8+qrow)*20 + kt*8 + qcol];
            unsigned bb1 = W0U[(nt*8+qrow)*20 + kt*8 + 4 + qcol];
            MMA_TF32(acc[nt][0],acc[nt][1],acc[nt][2],acc[nt][3],a0,a1,a2,a3,bb0,bb1);
        }
    }
    #pragma unroll
    for (int nt = 0; nt < 16; ++nt) {
        X1U[(rbase+qrow  )*132 + nt*8 + 2*qcol    ] = f2tf32(fmaxf(acc[nt][0], 0.f));
        X1U[(rbase+qrow  )*132 + nt*8 + 2*qcol + 1] = f2tf32(fmaxf(acc[nt][1], 0.f));
        X1U[(rbase+qrow+8)*132 + nt*8 + 2*qcol    ] = f2tf32(fmaxf(acc[nt][2], 0.f));
        X1U[(rbase+qrow+8)*132 + nt*8 + 2*qcol + 1] = f2tf32(fmaxf(acc[nt][3], 0.f));
    }
    __syncthreads();

    // layer 2: 128 -> 128 (relu)
    #pragma unroll
    for (int nt = 0; nt < 16; ++nt) {
        float bv0 = B1S[nt*8 + 2*qcol], bv1 = B1S[nt*8 + 2*qcol + 1];
        acc[nt][0] = bv0; acc[nt][1] = bv1; acc[nt][2] = bv0; acc[nt][3] = bv1;
    }
    #pragma unroll
    for (int kt = 0; kt < 16; ++kt) {
        unsigned a0 = X1U[(rbase+qrow  )*132 + kt*8 + qcol];
        unsigned a1 = X1U[(rbase+qrow+8)*132 + kt*8 + qcol];
        unsigned a2 = X1U[(rbase+qrow  )*132 + kt*8 + 4 + qcol];
        unsigned a3 = X1U[(rbase+qrow+8)*132 + kt*8 + 4 + qcol];
        #pragma unroll
        for (int nt = 0; nt < 16; ++nt) {
            unsigned bb0 = W1U[(nt*8+qrow)*132 + kt*8 + qcol];
            unsigned bb1 = W1U[(nt*8+qrow)*132 + kt*8 + 4 + qcol];
            MMA_TF32(acc[nt][0],acc[nt][1],acc[nt][2],acc[nt][3],a0,a1,a2,a3,bb0,bb1);
        }
    }
    __syncthreads();  // all warps done reading X1U

    // pack relu outputs as half2 into smem
    __half2* H = (__half2*)X1U;
    #pragma unroll
    for (int nt = 0; nt < 16; ++nt) {
        H[(rbase+qrow  )*68 + nt*4 + qcol] =
            __floats2half2_rn(fmaxf(acc[nt][0],0.f), fmaxf(acc[nt][1],0.f));
        H[(rbase+qrow+8)*68 + nt*4 + qcol] =
            __floats2half2_rn(fmaxf(acc[nt][2],0.f), fmaxf(acc[nt][3],0.f));
    }
    __syncthreads();
    // transposed store: logical row (b,i,j) -> slot (b,j,i); 16B chunks
    for (int idx = t; idx < 2048; idx += 256) {
        int r = idx >> 4, chunk = idx & 15;
        int row = row0 + r;
        int b = row / 2304; int rem = row - b*2304;
        int i = rem / 48;   int j = rem - i*48;
        uint4 v = *(const uint4*)((const char*)(H + r*68) + chunk*16);
        *(uint4*)(d_r2h + (size_t)((b*48 + j)*48 + i)*128 + chunk*8) = v;
    }
}

// -------- fused layer: one (b,j) per CTA, 192 threads --------
__global__ void __launch_bounds__(192) layer_kernel(int inbuf, int outbuf, int last,
        const float* __restrict__ bih, const float* __restrict__ bhh) {
    const float* h_in   = (inbuf  == 0) ? d_hf  : ((inbuf  == 1) ? d_hA  : d_hB);
    const float* h_inT  = (inbuf  == 0) ? d_hfT : ((inbuf  == 1) ? d_hAT : d_hBT);
    float*       h_out  = (outbuf == 1) ? d_hA  : d_hB;
    float*       h_outT = (outbuf == 1) ? d_hAT : d_hBT;
    int j = blockIdx.x; int b = blockIdx.y;
    int t = threadIdx.x;
    int bj = b*48 + j;
    int k0 = (4*j)/3;
    int a64 = (16*j) % 48;            // = (64j mod 48), in {0,16,32}
    int sel = (48 - a64)/16 - 1;      // 0->2, 16->1, 32->0

    __shared__ float a_s[48][2];
    __shared__ float hold[64];
    __shared__ float4 Ppart[2][64];
    __shared__ float2 Pst[128];
    __shared__ float part[2][64];
    __shared__ float aggs[64];
    __shared__ float gis[192];
    __shared__ float hnew[64];
    __shared__ float Qs[2];

    // ---- Phase A: coalesced gather via transposed h + gT; own-node hidden ----
    if (t < 96) {
        int s = t / 48, i = t % 48;
        float hv = __ldg(&h_inT[(k0+s)*768 + b*48 + i]);
        float gv = __ldg(&d_gT[bj*48 + i]);
        a_s[i][s] = gv * hv;
    } else if (t < 160) {
        int c = t - 96;
        hold[c] = h_in[bj*64 + c];
    }
    __syncthreads();

    // ---- Phase B: fp16 P reduction (t<128, 2-way i split); Q on t in [128,130) ----
    if (t < 128) {
        int cp = t & 63, ih = t >> 6;
        const __half2* r2p = (const __half2*)(d_r2h + (size_t)bj*6144) + cp;
        float p00 = 0.f, p01 = 0.f, p10 = 0.f, p11 = 0.f;
        int ibeg = ih*24;
        #pragma unroll 8
        for (int i = ibeg; i < ibeg + 24; ++i) {
            float2 r2v = __half22float2(__ldg(&r2p[i*64]));
            float a0 = a_s[i][0], a1 = a_s[i][1];
            p00 += a0*r2v.x; p01 += a0*r2v.y;
            p10 += a1*r2v.x; p11 += a1*r2v.y;
        }
        Ppart[ih][cp] = make_float4(p00, p01, p10, p11);
    } else if (t < 130) {
        int s = t - 128;
        float q = 0.f;
        #pragma unroll
        for (int i = 0; i < 48; ++i) q += a_s[i][s];
        Qs[s] = q;
    }
    __syncthreads();
    if (t < 128) {
        int c = t, cp = c >> 1, lo = c & 1;
        float4 A = Ppart[0][cp], B = Ppart[1][cp];
        Pst[c] = lo ? make_float2(A.y + B.y, A.w + B.w)
                    : make_float2(A.x + B.x, A.z + B.z);
    }
    __syncthreads();

    // ---- Phase C: agg part via float4 c-pair SP table (32 iters) ----
    if (t < 128) {
        int m = t & 63, half = t >> 6;
        const float4* SPq = d_SPq + (sel*64)*64 + m;
        float acc = 0.f;
        int cqb = half*32;
        #pragma unroll 4
        for (int cq = cqb; cq < cqb + 32; ++cq) {
            float4 sp = __ldg(&SPq[cq*64]);
            float2 p0 = Pst[2*cq], p1 = Pst[2*cq+1];
            acc += sp.x*p0.x + sp.y*p0.y + sp.z*p1.x + sp.w*p1.y;
        }
        part[half][m] = acc;
    }
    __syncthreads();
    if (t < 64) {
        float2 bp = __ldg(&d_SPb[sel*64 + t]);
        aggs[t] = part[0][t] + part[1][t] + bp.x*Qs[0] + bp.y*Qs[1];
    }
    __syncthreads();

    // ---- Phase D: gi[gc] = Wih.agg via float4 k-quads (16 iters) ----
    {
        int gc = t;
        float acc = 0.f;
        #pragma unroll 4
        for (int kq = 0; kq < 16; ++kq) {
            float4 w = __ldg(&d_wihq[kq*192 + gc]);
            acc += w.x*aggs[4*kq] + w.y*aggs[4*kq+1]
                 + w.z*aggs[4*kq+2] + w.w*aggs[4*kq+3];
        }
        gis[gc] = acc;
    }
    __syncthreads();

    // ---- Phase E1: GRU combine (gh pipelined from previous layer / megaprep) ----
    if (t < 64) {
        int c = t;
        float gh0 = __ldg(&d_gh[bj*192 + c]);
        float gh1 = __ldg(&d_gh[bj*192 + 64 + c]);
        float gh2 = __ldg(&d_gh[bj*192 + 128 + c]);
        float r = 1.f/(1.f+expf(-(gis[c]      + bih[c]      + gh0)));
        float z = 1.f/(1.f+expf(-(gis[64+c]   + bih[64+c]   + gh1)));
        float n = tanhf(gis[128+c] + bih[128+c] + r*gh2);
        float hn = (1.f-z)*n + z*hold[c];
        float hm = d_mask[bj]*hn;
        h_out[bj*64 + c] = hm;
        h_outT[c*768 + bj] = hm;
        hnew[c] = hm;
    }
    if (!last) {
        __syncthreads();
        // ---- Phase E2: gh for NEXT layer: Whh.h_new + bhh (16 iters) ----
        int gc = t;
        float acc = 0.f;
        #pragma unroll 4
        for (int kq = 0; kq < 16; ++kq) {
            float4 w = __ldg(&d_whhq[kq*192 + gc]);
            acc += w.x*hnew[4*kq] + w.y*hnew[4*kq+1]
                 + w.z*hnew[4*kq+2] + w.w*hnew[4*kq+3];
        }
        d_gh[bj*192 + gc] = acc + bhh[gc];
    }
}

// -------- readout: 4 nodes per CTA, float4 over rows, k-quad packed weights --------
__global__ void __launch_bounds__(128) readout_kernel(
   const float* __restrict__ r0b0, const float* __restrict__ r0b1,
   const float* __restrict__ r0b2, const float* __restrict__ r1b0,
   const float* __restrict__ r1b1, const float* __restrict__ r1b2) {
    __shared__ float4 xinv[128];
    __shared__ float4 bufA[128];
    __shared__ float4 bufB[128];
    int c = threadIdx.x;
    int n0 = blockIdx.x * 4;
    {
        float v[4];
        #pragma unroll
        for (int r = 0; r < 4; ++r)
            v[r] = (c < 64) ? d_hf[(n0+r)*64 + c] : d_hA[(n0+r)*64 + (c-64)];
        xinv[c] = make_float4(v[0], v[1], v[2], v[3]);
    }
    __syncthreads();

    float4 acc;
    // Net0 L1 (128->128 relu)
    { float b = r0b0[c]; acc = make_float4(b,b,b,b); }
    #pragma unroll 4
    for (int kq = 0; kq < 32; ++kq) {
        float4 w = __ldg(&d_q0w0[kq*128 + c]);
        float4 x0 = xinv[4*kq], x1 = xinv[4*kq+1], x2 = xinv[4*kq+2], x3 = xinv[4*kq+3];
        acc.x += w.x*x0.x + w.y*x1.x + w.z*x2.x + w.w*x3.x;
        acc.y += w.x*x0.y + w.y*x1.y + w.z*x2.y + w.w*x3.y;
        acc.z += w.x*x0.z + w.y*x1.z + w.z*x2.z + w.w*x3.z;
        acc.w += w.x*x0.w + w.y*x1.w + w.z*x2.w + w.w*x3.w;
    }
    bufA[c] = make_float4(fmaxf(acc.x,0.f), fmaxf(acc.y,0.f), fmaxf(acc.z,0.f), fmaxf(acc.w,0.f));
    __syncthreads();
    // Net0 L2
    { float b = r0b1[c]; acc = make_float4(b,b,b,b); }
    #pragma unroll 4
    for (int kq = 0; kq < 32; ++kq) {
        float4 w = __ldg(&d_q0w1[kq*128 + c]);
        float4 x0 = bufA[4*kq], x1 = bufA[4*kq+1], x2 = bufA[4*kq+2], x3 = bufA[4*kq+3];
        acc.x += w.x*x0.x + w.y*x1.x + w.z*x2.x + w.w*x3.x;
        acc.y += w.x*x0.y + w.y*x1.y + w.z*x2.y + w.w*x3.y;
        acc.z += w.x*x0.z + w.y*x1.z + w.z*x2.z + w.w*x3.z;
        acc.w += w.x*x0.w + w.y*x1.w + w.z*x2.w + w.w*x3.w;
    }
    bufB[c] = make_float4(fmaxf(acc.x,0.f), fmaxf(acc.y,0.f), fmaxf(acc.z,0.f), fmaxf(acc.w,0.f));
    __syncthreads();
    // Net0 L3 (linear)
    float4 out0;
    { float b = r0b2[c]; out0 = make_float4(b,b,b,b); }
    #pragma unroll 4
    for (int kq = 0; kq < 32; ++kq) {
        float4 w = __ldg(&d_q0w2[kq*128 + c]);
        float4 x0 = bufB[4*kq], x1 = bufB[4*kq+1], x2 = bufB[4*kq+2], x3 = bufB[4*kq+3];
        out0.x += w.x*x0.x + w.y*x1.x + w.z*x2.x + w.w*x3.x;
        out0.y += w.x*x0.y + w.y*x1.y + w.z*x2.y + w.w*x3.y;
        out0.z += w.x*x0.z + w.y*x1.z + w.z*x2.z + w.w*x3.z;
        out0.w += w.x*x0.w + w.y*x1.w + w.z*x2.w + w.w*x3.w;
    }
    // Net1 L1 (64->128 relu) from hT half of xinv
    { float b = r1b0[c]; acc = make_float4(b,b,b,b); }
    #pragma unroll 4
    for (int kq = 0; kq < 16; ++kq) {
        float4 w = __ldg(&d_q1w0[kq*128 + c]);
        float4 x0 = xinv[64+4*kq], x1 = xinv[64+4*kq+1], x2 = xinv[64+4*kq+2], x3 = xinv[64+4*kq+3];
        acc.x += w.x*x0.x + w.y*x1.x + w.z*x2.x + w.w*x3.x;
        acc.y += w.x*x0.y + w.y*x1.y + w.z*x2.y + w.w*x3.y;
        acc.z += w.x*x0.z + w.y*x1.z + w.z*x2.z + w.w*x3.z;
        acc.w += w.x*x0.w + w.y*x1.w + w.z*x2.w + w.w*x3.w;
    }
    __syncthreads();
    bufA[c] = make_float4(fmaxf(acc.x,0.f), fmaxf(acc.y,0.f), fmaxf(acc.z,0.f), fmaxf(acc.w,0.f));
    __syncthreads();
    // Net1 L2
    { float b = r1b1[c]; acc = make_float4(b,b,b,b); }
    #pragma unroll 4
    for (int kq = 0; kq < 32; ++kq) {
        float4 w = __ldg(&d_q1w1[kq*128 + c]);
        float4 x0 = bufA[4*kq], x1 = bufA[4*kq+1], x2 = bufA[4*kq+2], x3 = bufA[4*kq+3];
        acc.x += w.x*x0.x + w.y*x1.x + w.z*x2.x + w.w*x3.x;
        acc.y += w.x*x0.y + w.y*x1.y + w.z*x2.y + w.w*x3.y;
        acc.z += w.x*x0.z + w.y*x1.z + w.z*x2.z + w.w*x3.z;
        acc.w += w.x*x0.w + w.y*x1.w + w.z*x2.w + w.w*x3.w;
    }
    __syncthreads();
    bufB[c] = make_float4(fmaxf(acc.x,0.f), fmaxf(acc.y,0.f), fmaxf(acc.z,0.f), fmaxf(acc.w,0.f));
    __syncthreads();
    // Net1 L3 (linear), multiply, mask, store
    float4 out1;
    { float b = r1b2[c]; out1 = make_float4(b,b,b,b); }
    #pragma unroll 4
    for (int kq = 0; kq < 32; ++kq) {
        float4 w = __ldg(&d_q1w2[kq*128 + c]);
        float4 x0 = bufB[4*kq], x1 = bufB[4*kq+1], x2 = bufB[4*kq+2], x3 = bufB[4*kq+3];
        out1.x += w.x*x0.x + w.y*x1.x + w.z*x2.x + w.w*x3.x;
        out1.y += w.x*x0.y + w.y*x1.y + w.z*x2.y + w.w*x3.y;
        out1.z += w.x*x0.z + w.y*x1.z + w.z*x2.z + w.w*x3.z;
        out1.w += w.x*x0.w + w.y*x1.w + w.z*x2.w + w.w*x3.w;
    }
    d_tmp[(n0+0)*128 + c] = d_mask[n0+0]*out0.x*out1.x;
    d_tmp[(n0+1)*128 + c] = d_mask[n0+1]*out0.y*out1.y;
    d_tmp[(n0+2)*128 + c] = d_mask[n0+2]*out0.z*out1.z;
    d_tmp[(n0+3)*128 + c] = d_mask[n0+3]*out0.w*out1.w;
}

// -------- final node-sum + sigmoid --------
__global__ void reduce_kernel(float* __restrict__ out) {
    int b = blockIdx.x; int t = threadIdx.x;  // 128 threads
    float s = 0.f;
    #pragma unroll 4
    for (int j = 0; j < 48; ++j) s += d_tmp[(b*48+j)*128 + t];
    out[b*128+t] = 1.f/(1.f+expf(-s));
}

extern "C" void kernel_launch(void* const* d_in, const int* in_sizes, int n_in,
                              void* d_out, int out_size) {
    const float* g       = (const float*)d_in[0];
    const float* h0      = (const float*)d_in[1];
    const float* e       = (const float*)d_in[2];
    const float* msg_w0  = (const float*)d_in[3];
    const float* msg_b0  = (const float*)d_in[4];
    const float* msg_w1  = (const float*)d_in[5];
    const float* msg_b1  = (const float*)d_in[6];
    const float* msg_w2  = (const float*)d_in[7];
    const float* msg_b2  = (const float*)d_in[8];
    const float* gru_wih = (const float*)d_in[9];
    const float* gru_whh = (const float*)d_in[10];
    const float* gru_bih = (const float*)d_in[11];
    const float* gru_bhh = (const float*)d_in[12];
    const float* r0_w0   = (const float*)d_in[13];
    const float* r0_b0   = (const float*)d_in[14];
    const float* r0_w1   = (const float*)d_in[15];
    const float* r0_b1   = (const float*)d_in[16];
    const float* r0_w2   = (const float*)d_in[17];
    const float* r0_b2   = (const float*)d_in[18];
    const float* r1_w0   = (const float*)d_in[19];
    const float* r1_b0   = (const float*)d_in[20];
    const float* r1_w1   = (const float*)d_in[21];
    const float* r1_b1   = (const float*)d_in[22];
    const float* r1_w2   = (const float*)d_in[23];
    const float* r1_b2   = (const float*)d_in[24];
    float* out = (float*)d_out;

    cudaFuncSetAttribute(relu2_kernel, cudaFuncAttributeMaxDynamicSharedMemorySize, RELU2_SMEM);

    megaprep_kernel<<<511, 192>>>(msg_w2, msg_b2, gru_wih, gru_whh, gru_bhh,
                                  msg_w1, msg_w0, h0, g,
                                  r0_w0, r0_w1, r0_w2, r1_w0, r1_w1, r1_w2);
    relu2_kernel<<<NE/128, 256, RELU2_SMEM>>>(e, msg_b0, msg_b1);
    // L1: hf -> hA ; L2: hA -> hB ; L3: hB -> hA
    layer_kernel<<<dim3(48, 16), 192>>>(0, 1, 0, gru_bih, gru_bhh);
    layer_kernel<<<dim3(48, 16), 192>>>(1, 2, 0, gru_bih, gru_bhh);
    layer_kernel<<<dim3(48, 16), 192>>>(2, 1, 1, gru_bih, gru_bhh);
    readout_kernel<<<NNODE/4, 128>>>(r0_b0, r0_b1, r0_b2, r1_b0, r1_b1, r1_b2);
    reduce_kernel<<<NB, 128>>>(out);
}